// round 12
// baseline (speedup 1.0000x reference)
#include <cuda_runtime.h>

#define NW      10000
#define MAXLEN  14
#define QCOUNT  32     // BSZ*SEQ
#define TPB     64
#define SORT_B  256
#define NWARPS  (SORT_B / 32)
#define NSB     ((NW + SORT_B - 1) / SORT_B)

// Scratch (no allocation allowed)
__device__ int   g_wlen_s[NW];
__device__ int   g_orig_s[NW];
__device__ uint4 g_packed[NW];
__device__ int   g_qorder[QCOUNT];

// -------------------------------------------------------------------------
// Fused counting-sort, DESCENDING length, ATOMIC-FREE histogram:
// per-thread register counters (packed all<<16 | before-block), REDUX warp
// reduction, smem cross-warp sum. Only atomics left: 1 rank-add per thread.
// Block 0 also emits g_qorder (descending swl; stable -> deterministic).
// -------------------------------------------------------------------------
__global__ void __launch_bounds__(SORT_B)
fused_sort_kernel(const int* __restrict__ words, const int* __restrict__ wl,
                  const int* __restrict__ x) {
    __shared__ unsigned int wh[NWARPS][16];
    __shared__ unsigned int h_allbef[16];   // packed: all<<16 | bef
    __shared__ int h_rank[16];
    __shared__ int base[16];

    const int t    = threadIdx.x;
    const int warp = t >> 5, lane = t & 31;
    const int blockStart = blockIdx.x * SORT_B;

    // Per-thread packed counters, statically indexed (registers, no atomics)
    unsigned int cnt[MAXLEN + 1];
    #pragma unroll
    for (int b = 1; b <= MAXLEN; ++b) cnt[b] = 0u;

    const uint4* wl4 = (const uint4*)wl;
    for (int v = t; v < NW / 4; v += SORT_B) {
        uint4 w4 = wl4[v];
        int idx = v * 4;
        unsigned int pk0 = 0x10000u + (unsigned)(idx + 0 < blockStart);
        unsigned int pk1 = 0x10000u + (unsigned)(idx + 1 < blockStart);
        unsigned int pk2 = 0x10000u + (unsigned)(idx + 2 < blockStart);
        unsigned int pk3 = 0x10000u + (unsigned)(idx + 3 < blockStart);
        #pragma unroll
        for (int b = 1; b <= MAXLEN; ++b) {
            cnt[b] += (w4.x == (unsigned)b) ? pk0 : 0u;
            cnt[b] += (w4.y == (unsigned)b) ? pk1 : 0u;
            cnt[b] += (w4.z == (unsigned)b) ? pk2 : 0u;
            cnt[b] += (w4.w == (unsigned)b) ? pk3 : 0u;
        }
    }

    // Warp-level reduction per bin, lane 0 publishes
    #pragma unroll
    for (int b = 1; b <= MAXLEN; ++b) {
        unsigned int r = __reduce_add_sync(0xFFFFFFFFu, cnt[b]);
        if (lane == 0) wh[warp][b] = r;
    }
    __syncthreads();

    if (t >= 1 && t <= MAXLEN) {
        unsigned int s = 0;
        #pragma unroll
        for (int w = 0; w < NWARPS; ++w) s += wh[w][t];
        h_allbef[t] = s;
        h_rank[t]   = 0;
    }
    __syncthreads();

    if (t == 0) {
        int acc = 0;
        for (int l = MAXLEN; l >= 1; --l) {             // descending lengths
            base[l] = acc;
            acc += (int)(h_allbef[l] >> 16);
        }
    }
    __syncthreads();

    const int w = blockStart + t;
    if (w < NW) {
        int len  = wl[w];
        int rank = atomicAdd(&h_rank[len], 1);
        int pos  = base[len] + (int)(h_allbef[len] & 0xFFFFu) + rank;
        g_wlen_s[pos] = len;
        g_orig_s[pos] = w;
        unsigned int p[4] = {0u, 0u, 0u, 0u};
        #pragma unroll
        for (int c = 0; c < MAXLEN; ++c) {
            unsigned int ch = (unsigned int)words[w * MAXLEN + c] & 0xFFu;
            p[c >> 2] |= ch << ((c & 3) * 8);
        }
        g_packed[pos] = make_uint4(p[0], p[1], p[2], p[3]);
    }

    // Block 0: q-order by descending swl (stable -> deterministic)
    if (blockIdx.x == 0) {
        __shared__ int s_swl[QCOUNT];
        if (t < QCOUNT) {
            int sw = 0, best = x[t * (MAXLEN + 1)];
            #pragma unroll
            for (int c = 1; c <= MAXLEN; ++c) {
                int v = x[t * (MAXLEN + 1) + c];
                if (v > best) { best = v; sw = c; }
            }
            s_swl[t] = sw;
        }
        __syncthreads();
        if (t == 0) {
            int ord[QCOUNT];
            for (int i = 0; i < QCOUNT; ++i) ord[i] = i;
            for (int i = 1; i < QCOUNT; ++i) {          // stable insertion sort, desc
                int o = ord[i], key = s_swl[o], m = i - 1;
                while (m >= 0 && s_swl[ord[m]] < key) { ord[m + 1] = ord[m]; --m; }
                ord[m + 1] = o;
            }
            for (int i = 0; i < QCOUNT; ++i) g_qorder[i] = ord[i];
        }
    }
}

// -------------------------------------------------------------------------
// Main kernel: EXACT R11 structure (26.8us / 64 regs proven). One thread per
// (query, sorted word). Previous DP row in registers; 14x16 per-thread byte
// matrix in smem serves only the transposition gather d[k][l]
// (k<=swl-1<=13, l<=wlen-1<=13). q = g_qorder[blockIdx.y] (heavy-first).
// -------------------------------------------------------------------------
__global__ void __launch_bounds__(TPB)
dl_kernel(const int* __restrict__ x, float* __restrict__ out) {
    __shared__ unsigned char d_s[14 * 16 * TPB];   // 224 B per thread
    __shared__ int s_x[MAXLEN + 1];

    const int tid  = threadIdx.x;
    const int q    = g_qorder[blockIdx.y];
    const int slot = blockIdx.x * TPB + tid;

    if (tid < MAXLEN + 1) s_x[tid] = x[q * (MAXLEN + 1) + tid];
    __syncthreads();

    // swl = first-argmax over the 15 chars (jnp.argmax semantics)
    int swl = 0, best = s_x[0];
    #pragma unroll
    for (int t = 1; t <= MAXLEN; ++t) {
        int v = s_x[t];
        if (v > best) { best = v; swl = t; }
    }

    int wlen = 0, orig = 0;
    unsigned int pw0 = 0, pw1 = 0, pw2 = 0, pw3 = 0;
    if (slot < NW) {
        wlen = g_wlen_s[slot];
        orig = g_orig_s[slot];
        uint4 p = g_packed[slot];
        pw0 = p.x; pw1 = p.y; pw2 = p.z; pw3 = p.w;
    }

    int wc[MAXLEN];
    #pragma unroll
    for (int c = 0; c < MAXLEN; ++c) {
        unsigned int r = (c < 4) ? pw0 : (c < 8) ? pw1 : (c < 12) ? pw2 : pw3;
        wc[c] = (int)((r >> ((c & 3) * 8)) & 0xFFu);
    }
    int kreg[MAXLEN];
    #pragma unroll
    for (int c = 0; c < MAXLEN; ++c) kreg[c] = 0;

    const int maxd = swl + wlen;
    unsigned char* bp = d_s + tid;

    // Init gather-reachable boundary cells (rows 0..swl-1, cols 0..wlen-1):
    //   d[0][l] = maxd ; d[1][0] = maxd ; d[1][l>=1] = l-1
    //   d[k][0] = maxd, d[k][1] = k-1   for k = 2..swl-1
    for (int l = 0; l < wlen; ++l) {
        bp[(0 * 16 + l) * TPB] = (unsigned char)maxd;
        bp[(1 * 16 + l) * TPB] = (unsigned char)(l == 0 ? maxd : l - 1);
    }
    for (int k = 2; k < swl; ++k) {
        bp[(k * 16 + 0) * TPB] = (unsigned char)maxd;
        bp[(k * 16 + 1) * TPB] = (unsigned char)(k - 1);
    }

    // prev[j] = d[i][j]; row 1: d[1][j] = j-1
    int prev[16];
    #pragma unroll
    for (int j = 1; j <= 15; ++j) prev[j] = j - 1;

    int res = wlen;                        // swl == 0: d[1][wlen+1] = wlen
    const int rlimit = swl - 2;            // last row whose store matters
    const int climit = wlen - 2;           // last col whose store matters
    for (int i = 1; i <= swl; ++i) {       // uniform per block
        const int xc  = s_x[i - 1];
        const int im1 = i - 1;
        int db   = 0;
        int left = i;                      // d[i+1][1] = i
        unsigned char* rowp = bp + ((i + 1) * 16) * TPB;
        const bool rkeep = (i <= rlimit);
        #pragma unroll
        for (int j = 1; j <= 15; ++j) {
            if (j > wlen || j == 15) { prev[j] = left; break; }   // d[i+1][j]
            const bool p  = (xc == wc[j - 1]);
            const int up   = prev[j + 1];
            const int diag = prev[j];
            const int k = kreg[j - 1];
            const int l = db;
            const int dtr   = (int)bp[(k * 16 + l) * TPB];        // LDS.U8
            const int trans = dtr + (im1 + j - k - l);
            int m = min(up, left) + 1;
            m = min(m, diag + (p ? 0 : 1));
            m = min(m, trans);
            if (p) { db = j; kreg[j - 1] = i; }
            if (rkeep && j <= climit)
                rowp[(j + 1) * TPB] = (unsigned char)m;           // d[i+1][j+1]
            prev[j] = left;
            left = m;
        }
        res = left;                        // d[i+1][wlen+1]
    }

    if (slot < NW) out[q * NW + orig] = (float)res;
}

// -------------------------------------------------------------------------
extern "C" void kernel_launch(void* const* d_in, const int* in_sizes, int n_in,
                              void* d_out, int out_size) {
    const int* x     = (const int*)d_in[0];   // (2,16,15) int32
    const int* words = (const int*)d_in[1];   // (10000,14) int32
    const int* wl    = (const int*)d_in[2];   // (10000,) int32
    float* out = (float*)d_out;               // (2,16,10000) float32

    fused_sort_kernel<<<NSB, SORT_B>>>(words, wl, x);
    dim3 grid((NW + TPB - 1) / TPB, QCOUNT);
    dl_kernel<<<grid, TPB>>>(x, out);
}

// round 13
// speedup vs baseline: 1.3122x; 1.3122x over previous
#include <cuda_runtime.h>

#define NW      10000
#define MAXLEN  14
#define QCOUNT  32     // BSZ*SEQ
#define TPB     64
#define SORT_B  256
#define NSB     ((NW + SORT_B - 1) / SORT_B)

// Scratch (no allocation allowed)
__device__ int   g_wlen_s[NW];
__device__ int   g_orig_s[NW];
__device__ uint4 g_packed[NW];
__device__ int   g_qorder[QCOUNT];

// -------------------------------------------------------------------------
// Fused counting-sort, DESCENDING length (heavy-first): R11's atomic
// histogram (proven faster than register-counter variant). Block 0 emits
// g_qorder via PARALLEL stable rank (R11's serial insertion sort cost
// ~10us of single-thread tail on the critical path).
// -------------------------------------------------------------------------
__global__ void __launch_bounds__(SORT_B)
fused_sort_kernel(const int* __restrict__ words, const int* __restrict__ wl,
                  const int* __restrict__ x) {
    __shared__ int h_all[MAXLEN + 2];
    __shared__ int h_bef[MAXLEN + 2];
    __shared__ int h_rank[MAXLEN + 2];
    __shared__ int base[MAXLEN + 2];

    const int t = threadIdx.x;
    const int blockStart = blockIdx.x * SORT_B;

    if (t <= MAXLEN + 1) { h_all[t] = 0; h_bef[t] = 0; h_rank[t] = 0; }
    __syncthreads();

    const uint4* wl4 = (const uint4*)wl;
    for (int v = t; v < NW / 4; v += SORT_B) {
        uint4 w4 = wl4[v];
        int idx = v * 4;
        atomicAdd(&h_all[w4.x], 1); if (idx + 0 < blockStart) atomicAdd(&h_bef[w4.x], 1);
        atomicAdd(&h_all[w4.y], 1); if (idx + 1 < blockStart) atomicAdd(&h_bef[w4.y], 1);
        atomicAdd(&h_all[w4.z], 1); if (idx + 2 < blockStart) atomicAdd(&h_bef[w4.z], 1);
        atomicAdd(&h_all[w4.w], 1); if (idx + 3 < blockStart) atomicAdd(&h_bef[w4.w], 1);
    }
    __syncthreads();

    if (t == 0) {
        int acc = 0;
        for (int l = MAXLEN; l >= 1; --l) { base[l] = acc; acc += h_all[l]; }  // descending
    }
    __syncthreads();

    const int w = blockStart + t;
    if (w < NW) {
        int len  = wl[w];
        int rank = atomicAdd(&h_rank[len], 1);
        int pos  = base[len] + h_bef[len] + rank;
        g_wlen_s[pos] = len;
        g_orig_s[pos] = w;
        unsigned int p[4] = {0u, 0u, 0u, 0u};
        #pragma unroll
        for (int c = 0; c < MAXLEN; ++c) {
            unsigned int ch = (unsigned int)words[w * MAXLEN + c] & 0xFFu;
            p[c >> 2] |= ch << ((c & 3) * 8);
        }
        g_packed[pos] = make_uint4(p[0], p[1], p[2], p[3]);
    }

    // Block 0: q-order by descending swl — PARALLEL stable rank.
    // rank(t) = #{j: swl[j] > swl[t]} + #{j < t: swl[j] == swl[t]}
    if (blockIdx.x == 0) {
        __shared__ int s_swl[QCOUNT];
        if (t < QCOUNT) {
            int sw = 0, best = x[t * (MAXLEN + 1)];
            #pragma unroll
            for (int c = 1; c <= MAXLEN; ++c) {
                int v = x[t * (MAXLEN + 1) + c];
                if (v > best) { best = v; sw = c; }
            }
            s_swl[t] = sw;
        }
        __syncthreads();
        if (t < QCOUNT) {
            int mine = s_swl[t];
            int rank = 0;
            #pragma unroll
            for (int j = 0; j < QCOUNT; ++j) {
                int sj = s_swl[j];
                rank += (sj > mine) || (sj == mine && j < t);
            }
            g_qorder[rank] = t;
        }
    }
}

// -------------------------------------------------------------------------
// Main kernel: EXACT R11/R12 structure (26.0us / 64 regs proven). One thread
// per (query, sorted word). Previous DP row in registers; 14x16 per-thread
// byte matrix in smem serves only the transposition gather d[k][l]
// (k<=swl-1<=13, l<=wlen-1<=13). q = g_qorder[blockIdx.y] (heavy-first).
// -------------------------------------------------------------------------
__global__ void __launch_bounds__(TPB)
dl_kernel(const int* __restrict__ x, float* __restrict__ out) {
    __shared__ unsigned char d_s[14 * 16 * TPB];   // 224 B per thread
    __shared__ int s_x[MAXLEN + 1];

    const int tid  = threadIdx.x;
    const int q    = g_qorder[blockIdx.y];
    const int slot = blockIdx.x * TPB + tid;

    if (tid < MAXLEN + 1) s_x[tid] = x[q * (MAXLEN + 1) + tid];
    __syncthreads();

    // swl = first-argmax over the 15 chars (jnp.argmax semantics)
    int swl = 0, best = s_x[0];
    #pragma unroll
    for (int t = 1; t <= MAXLEN; ++t) {
        int v = s_x[t];
        if (v > best) { best = v; swl = t; }
    }

    int wlen = 0, orig = 0;
    unsigned int pw0 = 0, pw1 = 0, pw2 = 0, pw3 = 0;
    if (slot < NW) {
        wlen = g_wlen_s[slot];
        orig = g_orig_s[slot];
        uint4 p = g_packed[slot];
        pw0 = p.x; pw1 = p.y; pw2 = p.z; pw3 = p.w;
    }

    int wc[MAXLEN];
    #pragma unroll
    for (int c = 0; c < MAXLEN; ++c) {
        unsigned int r = (c < 4) ? pw0 : (c < 8) ? pw1 : (c < 12) ? pw2 : pw3;
        wc[c] = (int)((r >> ((c & 3) * 8)) & 0xFFu);
    }
    int kreg[MAXLEN];
    #pragma unroll
    for (int c = 0; c < MAXLEN; ++c) kreg[c] = 0;

    const int maxd = swl + wlen;
    unsigned char* bp = d_s + tid;

    // Init gather-reachable boundary cells (rows 0..swl-1, cols 0..wlen-1):
    //   d[0][l] = maxd ; d[1][0] = maxd ; d[1][l>=1] = l-1
    //   d[k][0] = maxd, d[k][1] = k-1   for k = 2..swl-1
    for (int l = 0; l < wlen; ++l) {
        bp[(0 * 16 + l) * TPB] = (unsigned char)maxd;
        bp[(1 * 16 + l) * TPB] = (unsigned char)(l == 0 ? maxd : l - 1);
    }
    for (int k = 2; k < swl; ++k) {
        bp[(k * 16 + 0) * TPB] = (unsigned char)maxd;
        bp[(k * 16 + 1) * TPB] = (unsigned char)(k - 1);
    }

    // prev[j] = d[i][j]; row 1: d[1][j] = j-1
    int prev[16];
    #pragma unroll
    for (int j = 1; j <= 15; ++j) prev[j] = j - 1;

    int res = wlen;                        // swl == 0: d[1][wlen+1] = wlen
    const int rlimit = swl - 2;            // last row whose store matters
    const int climit = wlen - 2;           // last col whose store matters
    for (int i = 1; i <= swl; ++i) {       // uniform per block
        const int xc  = s_x[i - 1];
        const int im1 = i - 1;
        int db   = 0;
        int left = i;                      // d[i+1][1] = i
        unsigned char* rowp = bp + ((i + 1) * 16) * TPB;
        const bool rkeep = (i <= rlimit);
        #pragma unroll
        for (int j = 1; j <= 15; ++j) {
            if (j > wlen || j == 15) { prev[j] = left; break; }   // d[i+1][j]
            const bool p  = (xc == wc[j - 1]);
            const int up   = prev[j + 1];
            const int diag = prev[j];
            const int k = kreg[j - 1];
            const int l = db;
            const int dtr   = (int)bp[(k * 16 + l) * TPB];        // LDS.U8
            const int trans = dtr + (im1 + j - k - l);
            int m = min(up, left) + 1;
            m = min(m, diag + (p ? 0 : 1));
            m = min(m, trans);
            if (p) { db = j; kreg[j - 1] = i; }
            if (rkeep && j <= climit)
                rowp[(j + 1) * TPB] = (unsigned char)m;           // d[i+1][j+1]
            prev[j] = left;
            left = m;
        }
        res = left;                        // d[i+1][wlen+1]
    }

    if (slot < NW) out[q * NW + orig] = (float)res;
}

// -------------------------------------------------------------------------
extern "C" void kernel_launch(void* const* d_in, const int* in_sizes, int n_in,
                              void* d_out, int out_size) {
    const int* x     = (const int*)d_in[0];   // (2,16,15) int32
    const int* words = (const int*)d_in[1];   // (10000,14) int32
    const int* wl    = (const int*)d_in[2];   // (10000,) int32
    float* out = (float*)d_out;               // (2,16,10000) float32

    fused_sort_kernel<<<NSB, SORT_B>>>(words, wl, x);
    dim3 grid((NW + TPB - 1) / TPB, QCOUNT);
    dl_kernel<<<grid, TPB>>>(x, out);
}